// round 3
// baseline (speedup 1.0000x reference)
#include <cuda_runtime.h>

// DeChunkLayer: B=4, L=4096, D=1024, fp32 in/out.
// out[b,l,:] = h_{plug[b,l]} where h_t = (1-p_s[t]) h_{t-1} + p_s[t]*hidden[b,t,:],
// p_s[t] = clip(boundary_prob[b, pos_of_t-th_boundary, 1], EPS, 1-EPS),
// plug[b,l] = cumsum(mask)[l]-1.
// NOTE reference quirk: the scan's u_t uses SORTED p but UNSORTED hidden[:, t, :].

#define EPS_F 1e-4f

static constexpr int B = 4;
static constexpr int L = 4096;
static constexpr int D = 1024;
static constexpr int D4 = D / 4;
static constexpr int CT = 64;                 // chunk length over boundary rank t
static constexpr int NCHUNK = L / CT;         // 64 (worst case Nb = L)

// Scratch (static device globals; no allocation at runtime)
__device__ float g_Hs[B][L][D];               // chunk-local scan values (worst case 64 MB)
__device__ float g_carry[B][NCHUNK][D];       // carry entering each chunk
__device__ float g_ps[B][L];                  // compacted clipped p by boundary rank t
__device__ float g_P[B][L];                   // inclusive within-chunk decay products
__device__ int   g_plug[B][L];                // cumsum(mask)-1 per token
__device__ int   g_Nb[B];                     // boundary count per batch

// ---------------------------------------------------------------------------
// K1: per-batch prefix sum of mask, compact p, within-chunk decay products.
// Self-detects mask serialization format (uint8 / int32 / float32).
// ---------------------------------------------------------------------------
__global__ __launch_bounds__(1024) void k_setup(const float* __restrict__ bp,
                                                const void* __restrict__ mask) {
    const int b = blockIdx.x;
    const int tid = threadIdx.x;              // 0..1023, 4 tokens each
    const int lane = tid & 31, warp = tid >> 5;

    // ---- mask format detection over first 4096 32-bit words (always in-bounds:
    // uint8 layout has exactly 4096 words; int32/float32 layouts have 16384).
    const unsigned int* mw = reinterpret_cast<const unsigned int*>(mask);
    int anyFloat = 0, nonBinary = 0;
    for (int i = tid; i < 4096; i += 1024) {
        unsigned int w = mw[i];
        anyFloat  |= (w == 0x3F800000u);
        nonBinary |= (w > 1u);
    }
    int haveFloat  = __syncthreads_or(anyFloat);
    int haveNonBin = __syncthreads_or(nonBinary);
    // fmt: 2 = float32 words, 1 = int32 words, 0 = packed uint8 bytes
    const int fmt = haveFloat ? 2 : (haveNonBin ? 0 : 1);

    // ---- read this thread's 4 mask values
    int cnt[4];
    if (fmt == 0) {
        uchar4 m4 = reinterpret_cast<const uchar4*>(mask)[b * 1024 + tid];
        cnt[0] = m4.x != 0; cnt[1] = m4.y != 0; cnt[2] = m4.z != 0; cnt[3] = m4.w != 0;
    } else {
        uint4 m4 = reinterpret_cast<const uint4*>(mask)[b * 1024 + tid];
        cnt[0] = m4.x != 0; cnt[1] = m4.y != 0; cnt[2] = m4.z != 0; cnt[3] = m4.w != 0;
    }
    int s = cnt[0] + cnt[1] + cnt[2] + cnt[3];

    __shared__ int warp_sums[32];
    __shared__ int sNb;

    // warp inclusive scan of per-thread sums
    int incl = s;
#pragma unroll
    for (int o = 1; o < 32; o <<= 1) {
        int v = __shfl_up_sync(0xffffffffu, incl, o);
        if (lane >= o) incl += v;
    }
    if (lane == 31) warp_sums[warp] = incl;
    __syncthreads();
    if (warp == 0) {
        int ws = warp_sums[lane];
#pragma unroll
        for (int o = 1; o < 32; o <<= 1) {
            int v = __shfl_up_sync(0xffffffffu, ws, o);
            if (lane >= o) ws += v;
        }
        warp_sums[lane] = ws;                 // inclusive across warps
    }
    __syncthreads();
    int warp_excl = (warp == 0) ? 0 : warp_sums[warp - 1];
    int run = warp_excl + (incl - s);         // exclusive prefix at thread's first token

    const int base = tid * 4;
#pragma unroll
    for (int k = 0; k < 4; ++k) {
        run += cnt[k];
        int l = base + k;
        g_plug[b][l] = run - 1;
        if (cnt[k]) {
            float p = bp[(b * L + l) * 2 + 1];
            p = fminf(fmaxf(p, EPS_F), 1.0f - EPS_F);
            g_ps[b][run - 1] = p;
        }
    }
    if (tid == 1023) { g_Nb[b] = run; sNb = run; }
    __syncthreads();

    const int Nb = sNb;
    // within-chunk inclusive decay products: P[t] = prod_{s=chunk_start..t} (1-p_s)
    if (tid < NCHUNK) {
        int t0 = tid * CT;
        if (t0 < Nb) {
            int t1 = min(t0 + CT, Nb);
            float prod = 1.0f;
            for (int t = t0; t < t1; ++t) {
                prod *= (1.0f - g_ps[b][t]);
                g_P[b][t] = prod;
            }
        }
    }
}

// ---------------------------------------------------------------------------
// K2a: chunk-local EMA scan (carry-in 0), write Hs
// ---------------------------------------------------------------------------
__global__ __launch_bounds__(256) void k_chunkscan(const float* __restrict__ hidden) {
    const int b = blockIdx.y;
    const int c = blockIdx.x;
    const int Nb = g_Nb[b];
    const int t0 = c * CT;
    if (t0 >= Nb) return;
    const int t1 = min(t0 + CT, Nb);

    __shared__ float s_p[CT];
    if (threadIdx.x < (t1 - t0)) s_p[threadIdx.x] = g_ps[b][t0 + threadIdx.x];
    __syncthreads();

    const int d4 = threadIdx.x;               // 0..255
    const float4* hid = reinterpret_cast<const float4*>(hidden + b * L * D);
    float4* Hs = reinterpret_cast<float4*>(&g_Hs[b][0][0]);

    float4 h = make_float4(0.f, 0.f, 0.f, 0.f);
#pragma unroll 4
    for (int t = t0; t < t1; ++t) {
        float p = s_p[t - t0];
        float dec = 1.0f - p;
        float4 x = hid[t * D4 + d4];
        h.x = fmaf(dec, h.x, p * x.x);
        h.y = fmaf(dec, h.y, p * x.y);
        h.z = fmaf(dec, h.z, p * x.z);
        h.w = fmaf(dec, h.w, p * x.w);
        Hs[t * D4 + d4] = h;
    }
}

// ---------------------------------------------------------------------------
// K2b: carry scan across chunks per (b, d)
// ---------------------------------------------------------------------------
__global__ __launch_bounds__(256) void k_carry() {
    const int b = blockIdx.y;
    const int d = blockIdx.x * 256 + threadIdx.x;   // 0..1023
    const int Nb = g_Nb[b];
    const int nch = (Nb + CT - 1) / CT;

    float carry = 0.0f;
#pragma unroll 4
    for (int c = 0; c < nch; ++c) {
        g_carry[b][c][d] = carry;
        int endt = min((c + 1) * CT, Nb) - 1;
        float A = g_P[b][endt];
        float U = g_Hs[b][endt][d];
        carry = fmaf(A, carry, U);
    }
}

// ---------------------------------------------------------------------------
// K3: gather + carry fix: out[b,l,d] = Hs[b,t,d] + P[b,t]*carry[b, t/CT, d]
// ---------------------------------------------------------------------------
__global__ __launch_bounds__(256) void k_out(float* __restrict__ out) {
    const int blk = blockIdx.x;               // b*L + l
    const int b = blk >> 12;                  // L = 4096
    const int l = blk & (L - 1);
    const int t = g_plug[b][l];
    const float Pv = g_P[b][t];
    const int c = t >> 6;                     // CT = 64
    const int d4 = threadIdx.x;

    const float4* HsR = reinterpret_cast<const float4*>(&g_Hs[b][t][0]);
    const float4* CrR = reinterpret_cast<const float4*>(&g_carry[b][c][0]);
    float4 hl = HsR[d4];
    float4 cy = CrR[d4];
    float4 o;
    o.x = fmaf(Pv, cy.x, hl.x);
    o.y = fmaf(Pv, cy.y, hl.y);
    o.z = fmaf(Pv, cy.z, hl.z);
    o.w = fmaf(Pv, cy.w, hl.w);
    reinterpret_cast<float4*>(out)[blk * D4 + d4] = o;
}

// ---------------------------------------------------------------------------
extern "C" void kernel_launch(void* const* d_in, const int* in_sizes, int n_in,
                              void* d_out, int out_size) {
    // Bind inputs by element count, not position (removes ordering assumption):
    //   hidden_states: B*L*D = 16777216, boundary_prob: B*L*2 = 32768,
    //   boundary_mask: B*L = 16384.
    const float* hidden = nullptr;
    const float* bp = nullptr;
    const void* mask = nullptr;
    for (int i = 0; i < n_in; ++i) {
        if (in_sizes[i] == B * L * D)      hidden = (const float*)d_in[i];
        else if (in_sizes[i] == B * L * 2) bp = (const float*)d_in[i];
        else if (in_sizes[i] == B * L)     mask = d_in[i];
    }
    float* out = (float*)d_out;

    k_setup<<<B, 1024>>>(bp, mask);
    k_chunkscan<<<dim3(NCHUNK, B), 256>>>(hidden);
    k_carry<<<dim3(D / 256, B), 256>>>();
    k_out<<<B * L, 256>>>(out);
}

// round 4
// speedup vs baseline: 1.3869x; 1.3869x over previous
#include <cuda_runtime.h>

// DeChunkLayer: B=4, L=4096, D=1024, fp32 in/out.
// h_t = (1-p_s[t]) h_{t-1} + p_s[t]*hidden[b,t,:];  out[b,l,:] = h_{plug[b,l]}.
// All tokens in segment [pos[t], pos[t+1]) share output row h_t (segment broadcast).

#define EPS_F 1e-4f

static constexpr int B = 4;
static constexpr int L = 4096;
static constexpr int D = 1024;
static constexpr int D4 = D / 4;
static constexpr int CT = 64;                 // chunk length over boundary rank t
static constexpr int NCHUNK = L / CT;         // 64 (worst case Nb = L)

// Scratch (static device globals; no allocation at runtime)
__device__ float g_Hs[B][L][D];               // chunk-local scan values
__device__ float g_carry[B][NCHUNK][D];       // carry entering each chunk
__device__ float g_ps[B][L];                  // compacted clipped p by boundary rank t
__device__ float g_P[B][L];                   // inclusive within-chunk decay products
__device__ int   g_pos[B][L];                 // token position of boundary rank t
__device__ int   g_Nb[B];                     // boundary count per batch

// ---------------------------------------------------------------------------
// K1: prefix sum of mask, compact p + positions, within-chunk decay products.
// ---------------------------------------------------------------------------
__global__ __launch_bounds__(1024) void k_setup(const float* __restrict__ bp,
                                                const void* __restrict__ mask) {
    const int b = blockIdx.x;
    const int tid = threadIdx.x;              // 0..1023, 4 tokens each
    const int lane = tid & 31, warp = tid >> 5;

    __shared__ float s_ps[L];                 // 16 KB compacted p
    __shared__ int warp_sums[32];
    __shared__ int sNb;

    // ---- mask format detection over first 4096 words (in-bounds for all layouts)
    const unsigned int* mw = reinterpret_cast<const unsigned int*>(mask);
    int anyFloat = 0, nonBinary = 0;
    for (int i = tid; i < 4096; i += 1024) {
        unsigned int w = mw[i];
        anyFloat  |= (w == 0x3F800000u);
        nonBinary |= (w > 1u);
    }
    int haveFloat  = __syncthreads_or(anyFloat);
    int haveNonBin = __syncthreads_or(nonBinary);
    const int fmt = haveFloat ? 2 : (haveNonBin ? 0 : 1);  // 2=f32, 1=i32, 0=u8

    int cnt[4];
    if (fmt == 0) {
        uchar4 m4 = reinterpret_cast<const uchar4*>(mask)[b * 1024 + tid];
        cnt[0] = m4.x != 0; cnt[1] = m4.y != 0; cnt[2] = m4.z != 0; cnt[3] = m4.w != 0;
    } else {
        uint4 m4 = reinterpret_cast<const uint4*>(mask)[b * 1024 + tid];
        cnt[0] = m4.x != 0; cnt[1] = m4.y != 0; cnt[2] = m4.z != 0; cnt[3] = m4.w != 0;
    }
    int s = cnt[0] + cnt[1] + cnt[2] + cnt[3];

    int incl = s;
#pragma unroll
    for (int o = 1; o < 32; o <<= 1) {
        int v = __shfl_up_sync(0xffffffffu, incl, o);
        if (lane >= o) incl += v;
    }
    if (lane == 31) warp_sums[warp] = incl;
    __syncthreads();
    if (warp == 0) {
        int ws = warp_sums[lane];
#pragma unroll
        for (int o = 1; o < 32; o <<= 1) {
            int v = __shfl_up_sync(0xffffffffu, ws, o);
            if (lane >= o) ws += v;
        }
        warp_sums[lane] = ws;
    }
    __syncthreads();
    int warp_excl = (warp == 0) ? 0 : warp_sums[warp - 1];
    int run = warp_excl + (incl - s);

    const int base = tid * 4;
#pragma unroll
    for (int k = 0; k < 4; ++k) {
        run += cnt[k];
        int l = base + k;
        if (cnt[k]) {
            float p = bp[(b * L + l) * 2 + 1];
            p = fminf(fmaxf(p, EPS_F), 1.0f - EPS_F);
            int t = run - 1;
            g_ps[b][t]  = p;
            s_ps[t]     = p;
            g_pos[b][t] = l;
        }
    }
    if (tid == 1023) { g_Nb[b] = run; sNb = run; }
    __syncthreads();

    const int Nb = sNb;
    // within-chunk inclusive decay products from smem (fully unrolled)
    if (tid < NCHUNK) {
        const int t0 = tid * CT;
        if (t0 < Nb) {
            float prod = 1.0f;
#pragma unroll
            for (int j = 0; j < CT; ++j) {
                int t = t0 + j;
                bool valid = (t < Nb);
                float p = valid ? s_ps[t] : 0.0f;
                prod *= (1.0f - p);
                if (valid) g_P[b][t] = prod;
            }
        }
    }
}

// ---------------------------------------------------------------------------
// K2a: chunk-local EMA scan (carry-in 0), write Hs. Software-pipelined.
// ---------------------------------------------------------------------------
__global__ __launch_bounds__(256) void k_chunkscan(const float* __restrict__ hidden) {
    const int b = blockIdx.y;
    const int c = blockIdx.x;
    const int Nb = g_Nb[b];
    const int t0 = c * CT;
    if (t0 >= Nb) return;
    const int t1 = min(t0 + CT, Nb);

    __shared__ float s_p[CT];
    if (threadIdx.x < CT) {
        int t = t0 + threadIdx.x;
        s_p[threadIdx.x] = (t < Nb) ? g_ps[b][t] : 0.0f;
    }
    __syncthreads();

    const int d4 = threadIdx.x;
    const float4* hid = reinterpret_cast<const float4*>(hidden + b * L * D) + d4;
    float4* Hs = reinterpret_cast<float4*>(&g_Hs[b][0][0]) + d4;

    float4 h = make_float4(0.f, 0.f, 0.f, 0.f);
    if (t1 - t0 == CT) {
        // full chunk: fixed trip count, unrolled for deep MLP
#pragma unroll 8
        for (int j = 0; j < CT; ++j) {
            int t = t0 + j;
            float p = s_p[j];
            float dec = 1.0f - p;
            float4 x = hid[t * D4];
            h.x = fmaf(dec, h.x, p * x.x);
            h.y = fmaf(dec, h.y, p * x.y);
            h.z = fmaf(dec, h.z, p * x.z);
            h.w = fmaf(dec, h.w, p * x.w);
            Hs[t * D4] = h;
        }
    } else {
        for (int t = t0; t < t1; ++t) {
            float p = s_p[t - t0];
            float dec = 1.0f - p;
            float4 x = hid[t * D4];
            h.x = fmaf(dec, h.x, p * x.x);
            h.y = fmaf(dec, h.y, p * x.y);
            h.z = fmaf(dec, h.z, p * x.z);
            h.w = fmaf(dec, h.w, p * x.w);
            Hs[t * D4] = h;
        }
    }
}

// ---------------------------------------------------------------------------
// K2b: carry across chunks via warp affine scan. One warp per (b,d);
// each lane composes 2 chunks, then 5-step shuffle scan.
// ---------------------------------------------------------------------------
__global__ __launch_bounds__(256) void k_carry() {
    const int warp = threadIdx.x >> 5;
    const int lane = threadIdx.x & 31;
    const int g = blockIdx.x * 8 + warp;      // 0..4095 = (b,d)
    const int b = g >> 10;
    const int d = g & 1023;
    const int Nb = g_Nb[b];

    const int c0 = 2 * lane, c1 = 2 * lane + 1;
    int e0 = min((c0 + 1) * CT, Nb) - 1;      // clamped chunk-end ranks
    int e1 = min((c1 + 1) * CT, Nb) - 1;
    float A0 = g_P[b][e0], U0 = g_Hs[b][e0][d];
    float A1 = g_P[b][e1], U1 = g_Hs[b][e1][d];

    // local compose (chunk c1 after c0)
    float A = A1 * A0;
    float U = fmaf(A1, U0, U1);

    // inclusive warp scan with affine composition
#pragma unroll
    for (int o = 1; o < 32; o <<= 1) {
        float pa = __shfl_up_sync(0xffffffffu, A, o);
        float pu = __shfl_up_sync(0xffffffffu, U, o);
        if (lane >= o) {
            U = fmaf(A, pu, U);
            A = A * pa;
        }
    }
    // exclusive value entering chunk c0
    float exclU = __shfl_up_sync(0xffffffffu, U, 1);
    if (lane == 0) exclU = 0.0f;

    g_carry[b][c0][d] = exclU;
    g_carry[b][c1][d] = fmaf(A0, exclU, U0);
}

// ---------------------------------------------------------------------------
// K3: segment broadcast. One block per boundary rank t:
// o = Hs[t] + P[t]*carry[t/CT]; write o to all rows [pos[t], pos[t+1]).
// ---------------------------------------------------------------------------
__global__ __launch_bounds__(256) void k_out(float* __restrict__ out) {
    const int b = blockIdx.y;
    const int t = blockIdx.x;
    const int Nb = g_Nb[b];
    if (t >= Nb) return;
    const int d4 = threadIdx.x;
    const int c = t >> 6;                     // CT = 64

    const float Pv = g_P[b][t];
    float4 hl = reinterpret_cast<const float4*>(&g_Hs[b][t][0])[d4];
    float4 cy = reinterpret_cast<const float4*>(&g_carry[b][c][0])[d4];
    float4 o;
    o.x = fmaf(Pv, cy.x, hl.x);
    o.y = fmaf(Pv, cy.y, hl.y);
    o.z = fmaf(Pv, cy.z, hl.z);
    o.w = fmaf(Pv, cy.w, hl.w);

    const int l0 = g_pos[b][t];
    const int l1 = (t + 1 < Nb) ? g_pos[b][t + 1] : L;
    float4* dst = reinterpret_cast<float4*>(out) + ((b << 12) + l0) * D4 + d4;
    for (int l = l0; l < l1; ++l, dst += D4) *dst = o;
}

// ---------------------------------------------------------------------------
extern "C" void kernel_launch(void* const* d_in, const int* in_sizes, int n_in,
                              void* d_out, int out_size) {
    const float* hidden = nullptr;
    const float* bp = nullptr;
    const void* mask = nullptr;
    for (int i = 0; i < n_in; ++i) {
        if (in_sizes[i] == B * L * D)      hidden = (const float*)d_in[i];
        else if (in_sizes[i] == B * L * 2) bp = (const float*)d_in[i];
        else if (in_sizes[i] == B * L)     mask = d_in[i];
    }
    float* out = (float*)d_out;

    k_setup<<<B, 1024>>>(bp, mask);
    k_chunkscan<<<dim3(NCHUNK, B), 256>>>(hidden);
    k_carry<<<B * D / 8, 256>>>();
    k_out<<<dim3(L, B), 256>>>(out);
}